// round 1
// baseline (speedup 1.0000x reference)
#include <cuda_runtime.h>
#include <math.h>

// Problem constants (fixed by the dataset)
#define BT      2048      // B*T tokens
#define BSEQ    4         // sequences
#define TSEQ    512       // tokens per sequence
#define HDIM    1024      // hidden
#define VOCAB   32000     // vocab
#define NCHUNK  10        // vocab chunks (gridDim.y)
#define CHUNK   3200      // vocab cols per chunk
#define TM      64        // token tile
#define TN      64        // vocab tile
#define KT      16        // k tile
#define IGNORE_INDEX (-100)
#define BETA    0.1f

// -------- device scratch (static: no allocations allowed) --------
__device__ float2 g_partials[2][NCHUNK * BT];  // per (pass, chunk, token): (max, sumexp)
__device__ float  g_tgt[2][BT];                // exact target logit (incl. bias)
__device__ float  g_seq[2][BSEQ];              // per-sequence summed logprob

// -------- target dtype detection: int64 vs int32 ----------------
__device__ __forceinline__ bool target_is_i64(const void* t) {
    const int* w = (const int*)t;   // safe: buffer >= 2048*4 bytes
    bool is64 = true;
    #pragma unroll
    for (int i = 0; i < 32; i++) {
        if (w[2 * i + 1] != 0) is64 = false;  // high words of int64 targets are 0
    }
    return is64;
}
__device__ __forceinline__ long long load_tgt(const void* t, int i, bool is64) {
    if (is64) return ((const long long*)t)[i];
    return (long long)((const int*)t)[i];
}

// =================================================================
// Kernel 1: fused GEMM + online (max, sumexp) per (token-tile, vocab-chunk)
//   grid: (BT/TM=32, NCHUNK=10, 2 passes), block 256
//   64x64 output tile, 4x4 per thread, K-tiled via transposed smem.
// =================================================================
__global__ __launch_bounds__(256)
void lse_partial_kernel(const float* __restrict__ x0, const float* __restrict__ w0,
                        const float* __restrict__ b0,
                        const float* __restrict__ x1, const float* __restrict__ w1,
                        const float* __restrict__ b1)
{
    const int pass = blockIdx.z;
    const float* __restrict__ X  = pass ? x1 : x0;
    const float* __restrict__ W  = pass ? w1 : w0;
    const float* __restrict__ BV = pass ? b1 : b0;

    // [k][row] layout; pad 68 keeps LDS.128 16B-aligned & compute conflict-free
    __shared__ __align__(16) float As[KT][68];
    __shared__ __align__(16) float Bs[KT][68];

    const int tid  = threadIdx.x;
    const int tx   = tid & 15;        // 16 col-groups
    const int ty   = tid >> 4;        // 16 row-groups
    const int lrow = tid >> 2;        // 0..63 load row
    const int lq   = tid & 3;         // 0..3 load quad
    const int m0   = blockIdx.x * TM;

    float runM[4], runS[4];
    #pragma unroll
    for (int i = 0; i < 4; i++) { runM[i] = -INFINITY; runS[i] = 0.0f; }

    const float* Xp = X + (size_t)(m0 + lrow) * HDIM + lq * 4;

    for (int nt = 0; nt < CHUNK / TN; nt++) {
        const int n0 = blockIdx.y * CHUNK + nt * TN;
        const float* Wp = W + (size_t)(n0 + lrow) * HDIM + lq * 4;

        float acc[4][4];
        #pragma unroll
        for (int i = 0; i < 4; i++)
            #pragma unroll
            for (int j = 0; j < 4; j++) acc[i][j] = 0.0f;

        for (int k0 = 0; k0 < HDIM; k0 += KT) {
            float4 av = *(const float4*)(Xp + k0);
            float4 bv = *(const float4*)(Wp + k0);
            __syncthreads();  // previous tile's compute done
            As[lq * 4 + 0][lrow] = av.x; As[lq * 4 + 1][lrow] = av.y;
            As[lq * 4 + 2][lrow] = av.z; As[lq * 4 + 3][lrow] = av.w;
            Bs[lq * 4 + 0][lrow] = bv.x; Bs[lq * 4 + 1][lrow] = bv.y;
            Bs[lq * 4 + 2][lrow] = bv.z; Bs[lq * 4 + 3][lrow] = bv.w;
            __syncthreads();
            #pragma unroll
            for (int kk = 0; kk < KT; kk++) {
                float4 a4 = *(const float4*)&As[kk][ty * 4];
                float4 b4 = *(const float4*)&Bs[kk][tx * 4];
                float ar[4] = {a4.x, a4.y, a4.z, a4.w};
                float br[4] = {b4.x, b4.y, b4.z, b4.w};
                #pragma unroll
                for (int i = 0; i < 4; i++)
                    #pragma unroll
                    for (int j = 0; j < 4; j++)
                        acc[i][j] = fmaf(ar[i], br[j], acc[i][j]);
            }
        }

        // bias + tile-local softmax stats, butterfly over the 16 tx lanes
        float4 bb = *(const float4*)&BV[n0 + tx * 4];
        float bj[4] = {bb.x, bb.y, bb.z, bb.w};
        #pragma unroll
        for (int i = 0; i < 4; i++) {
            float v0 = acc[i][0] + bj[0];
            float v1 = acc[i][1] + bj[1];
            float v2 = acc[i][2] + bj[2];
            float v3 = acc[i][3] + bj[3];
            float m = fmaxf(fmaxf(v0, v1), fmaxf(v2, v3));
            #pragma unroll
            for (int o = 1; o < 16; o <<= 1)
                m = fmaxf(m, __shfl_xor_sync(0xffffffffu, m, o));
            float s = __expf(v0 - m) + __expf(v1 - m) + __expf(v2 - m) + __expf(v3 - m);
            #pragma unroll
            for (int o = 1; o < 16; o <<= 1)
                s += __shfl_xor_sync(0xffffffffu, s, o);
            // online merge with running stats
            float nm = fmaxf(runM[i], m);
            runS[i] = runS[i] * __expf(runM[i] - nm) + s * __expf(m - nm);
            runM[i] = nm;
        }
    }

    if (tx == 0) {
        #pragma unroll
        for (int i = 0; i < 4; i++)
            g_partials[pass][blockIdx.y * BT + m0 + ty * 4 + i] =
                make_float2(runM[i], runS[i]);
    }
}

// =================================================================
// Kernel 2: exact fp32 target logits (both passes)
//   grid (BT, 2), block 128
// =================================================================
__global__ __launch_bounds__(128)
void tgt_logit_kernel(const float* __restrict__ x0, const float* __restrict__ w0,
                      const float* __restrict__ b0,
                      const float* __restrict__ x1, const float* __restrict__ w1,
                      const float* __restrict__ b1,
                      const void* __restrict__ tgt)
{
    const int pass = blockIdx.y;
    const float* X  = pass ? x1 : x0;
    const float* W  = pass ? w1 : w0;
    const float* BV = pass ? b1 : b0;
    const int tok = blockIdx.x;

    const bool is64 = target_is_i64(tgt);
    long long t = load_tgt(tgt, tok, is64);
    int tc = (int)t;
    tc = tc < 0 ? 0 : (tc >= VOCAB ? VOCAB - 1 : tc);  // safe_tgt clip

    const float4* xv = (const float4*)(X + (size_t)tok * HDIM);
    const float4* wv = (const float4*)(W + (size_t)tc * HDIM);
    float s = 0.0f;
    for (int c = threadIdx.x; c < HDIM / 4; c += blockDim.x) {
        float4 a = xv[c], b = wv[c];
        s += a.x * b.x + a.y * b.y + a.z * b.z + a.w * b.w;
    }
    #pragma unroll
    for (int o = 16; o; o >>= 1) s += __shfl_xor_sync(0xffffffffu, s, o);
    __shared__ float red[4];
    if ((threadIdx.x & 31) == 0) red[threadIdx.x >> 5] = s;
    __syncthreads();
    if (threadIdx.x == 0)
        g_tgt[pass][tok] = red[0] + red[1] + red[2] + red[3] + BV[tc];
}

// =================================================================
// Kernel 3: combine chunk partials -> per-token logprob -> per-seq sums
//   grid (BSEQ), block 256
// =================================================================
__global__ __launch_bounds__(256)
void combine_kernel(const void* __restrict__ tgt)
{
    const int b = blockIdx.x;
    const int tid = threadIdx.x;
    const bool is64 = target_is_i64(tgt);
    float accp = 0.0f, accr = 0.0f;

    for (int it = 0; it < TSEQ; it += 256) {
        const int tok = b * TSEQ + it + tid;
        long long t = load_tgt(tgt, tok, is64);
        if (t != IGNORE_INDEX) {
            #pragma unroll
            for (int p = 0; p < 2; p++) {
                float2 pc[NCHUNK];
                float M = -INFINITY;
                #pragma unroll
                for (int c = 0; c < NCHUNK; c++) {
                    pc[c] = g_partials[p][c * BT + tok];
                    M = fmaxf(M, pc[c].x);
                }
                float S = 0.0f;
                #pragma unroll
                for (int c = 0; c < NCHUNK; c++)
                    S += pc[c].y * __expf(pc[c].x - M);
                float lse = M + logf(S);
                float lp = g_tgt[p][tok] - lse;
                if (p == 0) accp += lp; else accr += lp;
            }
        }
    }
    #pragma unroll
    for (int o = 16; o; o >>= 1) {
        accp += __shfl_xor_sync(0xffffffffu, accp, o);
        accr += __shfl_xor_sync(0xffffffffu, accr, o);
    }
    __shared__ float sp[8], sr[8];
    if ((tid & 31) == 0) { sp[tid >> 5] = accp; sr[tid >> 5] = accr; }
    __syncthreads();
    if (tid == 0) {
        float a = 0.0f, r = 0.0f;
        #pragma unroll
        for (int i = 0; i < 8; i++) { a += sp[i]; r += sr[i]; }
        g_seq[0][b] = a;
        g_seq[1][b] = r;
    }
}

// =================================================================
// Kernel 4: final KTO loss + reward sums (single thread)
// =================================================================
__global__ void final_kernel(const void* __restrict__ pref,
                             const float* __restrict__ kl,
                             float* __restrict__ out, int out_size)
{
    if (threadIdx.x != 0) return;

    // preference_labels dtype detection: int32 {0,1} words vs packed bool bytes.
    const int* pw = (const int*)pref;
    bool isInt = true;
    int li[BSEQ];
    #pragma unroll
    for (int i = 0; i < BSEQ; i++) {
        int v = pw[i];
        if (v != 0 && v != 1) isInt = false;
        li[i] = v;
    }
    const unsigned char* pb = (const unsigned char*)pref;
    int lab[BSEQ];
    #pragma unroll
    for (int i = 0; i < BSEQ; i++)
        lab[i] = isInt ? li[i] : (pb[i] != 0 ? 1 : 0);

    const float kl0 = kl[0];
    float loss = 0.0f, ch = 0.0f, rj = 0.0f;
    #pragma unroll
    for (int b = 0; b < BSEQ; b++) {
        float lr   = g_seq[0][b] - g_seq[1][b];
        float mult = lab[b] ? 1.0f : -1.0f;
        float z    = BETA * (lr - kl0) * mult;
        loss += 1.0f - 1.0f / (1.0f + expf(-z));   // 1 - sigmoid(z)
        float rw = BETA * lr;
        if (lab[b]) ch += rw; else rj += rw;
    }
    loss /= (float)BT;
    if (out_size > 0) out[0] = loss;
    if (out_size > 1) out[1] = ch;
    if (out_size > 2) out[2] = rj;
}

// =================================================================
extern "C" void kernel_launch(void* const* d_in, const int* in_sizes, int n_in,
                              void* d_out, int out_size)
{
    const float* x    = (const float*)d_in[0];
    const float* w    = (const float*)d_in[1];
    const void*  tgt  = d_in[2];
    const float* bias = (const float*)d_in[3];
    const void*  pref = d_in[4];
    const float* xr   = (const float*)d_in[5];
    const float* wr   = (const float*)d_in[6];
    const float* br   = (const float*)d_in[7];
    const float* kl   = (const float*)d_in[8];

    dim3 g1(BT / TM, NCHUNK, 2);
    lse_partial_kernel<<<g1, 256>>>(x, w, bias, xr, wr, br);
    tgt_logit_kernel<<<dim3(BT, 2), 128>>>(x, w, bias, xr, wr, br, tgt);
    combine_kernel<<<BSEQ, 256>>>(tgt);
    final_kernel<<<1, 32>>>(pref, kl, (float*)d_out, out_size);
}

// round 3
// speedup vs baseline: 3.3839x; 3.3839x over previous
#include <cuda_runtime.h>
#include <cuda_bf16.h>
#include <math.h>
#include <stdint.h>

// ---------------- problem constants ----------------
#define BT      2048
#define BSEQ    4
#define TSEQ    512
#define HDIM    1024
#define VOCAB   32000
#define IGNORE_INDEX (-100)
#define BETA    0.1f

// GEMM tiling
#define TILE_M   128
#define TILE_N   128
#define KSTAGE   32                  // k elems per stage (64B rows)
#define NSTAGES  (HDIM / KSTAGE)     // 32
#define NTILES_M (BT / TILE_M)       // 16
#define NTILES_N (VOCAB / TILE_N)    // 250

// dynamic smem: 2 buffers x 4 tiles x (128 rows x 64B) = 64KB (+align slack)
#define TILE_BYTES   8192u
#define BUF_BYTES    (4u * TILE_BYTES)
#define SM_AH(b)  ((b) * BUF_BYTES + 0u)
#define SM_AL(b)  ((b) * BUF_BYTES + TILE_BYTES)
#define SM_BH(b)  ((b) * BUF_BYTES + 2u * TILE_BYTES)
#define SM_BL(b)  ((b) * BUF_BYTES + 3u * TILE_BYTES)
#define SMEM_DYN  (2u * BUF_BYTES + 1024u)

// ---------------- device scratch (static) ----------------
__device__ __nv_bfloat16 g_whi[2ULL * VOCAB * HDIM];
__device__ __nv_bfloat16 g_wlo[2ULL * VOCAB * HDIM];
__device__ __nv_bfloat16 g_xhi[2ULL * BT * HDIM];
__device__ __nv_bfloat16 g_xlo[2ULL * BT * HDIM];
__device__ float2 g_partials[2][(size_t)NTILES_N * BT];
__device__ float  g_tgt[2][BT];
__device__ float  g_seq[2][BSEQ];

// ---------------- helpers ----------------
__device__ __forceinline__ uint32_t smem_u32(const void* p) {
    uint32_t a;
    asm("{ .reg .u64 t; cvta.to.shared.u64 t, %1; cvt.u32.u64 %0, t; }" : "=r"(a) : "l"(p));
    return a;
}
// SW64 swizzle for 64B rows: XOR 16B-chunk bits[5:4] with row bits (off bits [8:7])
__device__ __forceinline__ uint32_t swz64(uint32_t off) {
    return off ^ ((off >> 3) & 0x30u);
}
__device__ __forceinline__ void ldmatrix_x4(uint32_t* r, uint32_t addr) {
    asm volatile("ldmatrix.sync.aligned.m8n8.x4.shared.b16 {%0,%1,%2,%3}, [%4];"
                 : "=r"(r[0]), "=r"(r[1]), "=r"(r[2]), "=r"(r[3]) : "r"(addr));
}
__device__ __forceinline__ void mma16816(float* d, const uint32_t* a,
                                         uint32_t b0, uint32_t b1) {
    asm volatile("mma.sync.aligned.m16n8k16.row.col.f32.bf16.bf16.f32 "
                 "{%0,%1,%2,%3}, {%4,%5,%6,%7}, {%8,%9}, {%0,%1,%2,%3};"
                 : "+f"(d[0]), "+f"(d[1]), "+f"(d[2]), "+f"(d[3])
                 : "r"(a[0]), "r"(a[1]), "r"(a[2]), "r"(a[3]), "r"(b0), "r"(b1));
}

// ---------------- dtype detection ----------------
__device__ __forceinline__ bool target_is_i64(const void* t) {
    const int* w = (const int*)t;
    bool is64 = true;
    #pragma unroll
    for (int i = 0; i < 32; i++)
        if (w[2 * i + 1] != 0) is64 = false;
    return is64;
}
__device__ __forceinline__ long long load_tgt(const void* t, int i, bool is64) {
    return is64 ? ((const long long*)t)[i] : (long long)((const int*)t)[i];
}

// =================================================================
// Kernel 0: fp32 -> (bf16 hi, bf16 lo) split
// =================================================================
__global__ __launch_bounds__(256)
void split_kernel(const float* __restrict__ src, __nv_bfloat16* __restrict__ hi,
                  __nv_bfloat16* __restrict__ lo, long long n4)
{
    long long stride = (long long)gridDim.x * blockDim.x;
    const float4* s4 = (const float4*)src;
    uint2* h2 = (uint2*)hi;
    uint2* l2 = (uint2*)lo;
    for (long long i = (long long)blockIdx.x * blockDim.x + threadIdx.x; i < n4; i += stride) {
        float4 v = s4[i];
        float f[4] = {v.x, v.y, v.z, v.w};
        unsigned short hs[4], ls[4];
        #pragma unroll
        for (int j = 0; j < 4; j++) {
            __nv_bfloat16 h = __float2bfloat16_rn(f[j]);
            float rem = f[j] - __bfloat162float(h);
            __nv_bfloat16 l = __float2bfloat16_rn(rem);
            hs[j] = __bfloat16_as_ushort(h);
            ls[j] = __bfloat16_as_ushort(l);
        }
        uint2 ho, lu;
        ho.x = (uint32_t)hs[0] | ((uint32_t)hs[1] << 16);
        ho.y = (uint32_t)hs[2] | ((uint32_t)hs[3] << 16);
        lu.x = (uint32_t)ls[0] | ((uint32_t)ls[1] << 16);
        lu.y = (uint32_t)ls[2] | ((uint32_t)ls[3] << 16);
        h2[i] = ho;
        l2[i] = lu;
    }
}

// =================================================================
// Kernel 1: HMMA (mma.sync bf16) GEMM + fused online-softmax partials
//   grid (16, 250, 2), block 256 (8 warps: 2m x 4n), warp tile 64x32
// =================================================================
__device__ __forceinline__ void cp_tile32(uint32_t dst, const __nv_bfloat16* src,
                                          int tid)
{
    // tile: 128 rows x 32 bf16 (64B rows), SW64-swizzled; 512 x 16B chunks
    #pragma unroll
    for (int i = 0; i < 2; i++) {
        int idx = tid + i * 256;
        int r = idx >> 2;
        int c = idx & 3;
        uint32_t off = (uint32_t)r * 64u + (uint32_t)c * 16u;
        const char* g = (const char*)src + (size_t)r * (HDIM * 2) + c * 16;
        asm volatile("cp.async.cg.shared.global [%0], [%1], 16;"
                     :: "r"(dst + swz64(off)), "l"(g) : "memory");
    }
}

__global__ __launch_bounds__(256, 1)
void lse_mma_kernel(const float* __restrict__ b0v, const float* __restrict__ b1v)
{
    extern __shared__ char dsm[];
    __shared__ float bias_sm[TILE_N];
    __shared__ float redM[4][TILE_M];
    __shared__ float redS[4][TILE_M];

    const int tid  = threadIdx.x;
    const int wid  = tid >> 5;
    const int lane = tid & 31;
    const int warp_m = wid & 1;        // 0..1
    const int warp_n = wid >> 1;       // 0..3

    uint32_t raw  = smem_u32(dsm);
    uint32_t base = (raw + 1023u) & ~1023u;

    const int m0   = blockIdx.x * TILE_M;
    const int n0   = blockIdx.y * TILE_N;
    const int pass = blockIdx.z;
    const float* BV = pass ? b1v : b0v;

    const __nv_bfloat16* Ah = g_xhi + ((size_t)pass * BT + m0) * HDIM;
    const __nv_bfloat16* Al = g_xlo + ((size_t)pass * BT + m0) * HDIM;
    const __nv_bfloat16* Bh = g_whi + ((size_t)pass * VOCAB + n0) * HDIM;
    const __nv_bfloat16* Bl = g_wlo + ((size_t)pass * VOCAB + n0) * HDIM;

    if (tid < TILE_N) bias_sm[tid] = BV[n0 + tid];

    // per-lane ldmatrix offsets (tile-relative, swizzled)
    // A: (mi, ks): row = warp_m*64 + mi*16 + (lane&15), kb = ks*32 + (lane>>4)*16
    uint32_t aoff[2][4], boff[2][2];
    #pragma unroll
    for (int ks = 0; ks < 2; ks++) {
        #pragma unroll
        for (int mi = 0; mi < 4; mi++) {
            uint32_t row = (uint32_t)(warp_m * 64 + mi * 16 + (lane & 15));
            uint32_t kb  = (uint32_t)(ks * 32 + (lane >> 4) * 16);
            aoff[ks][mi] = swz64(row * 64u + kb);
        }
        #pragma unroll
        for (int np = 0; np < 2; np++) {
            uint32_t n  = (uint32_t)(warp_n * 32 + np * 16 + ((lane >> 4) & 1) * 8 + (lane & 7));
            uint32_t kb = (uint32_t)(ks * 32 + ((lane >> 3) & 1) * 16);
            boff[ks][np] = swz64(n * 64u + kb);
        }
    }

    float acc[4][4][4];
    #pragma unroll
    for (int mi = 0; mi < 4; mi++)
        #pragma unroll
        for (int ni = 0; ni < 4; ni++)
            #pragma unroll
            for (int j = 0; j < 4; j++) acc[mi][ni][j] = 0.0f;

    // prologue: stage 0,1
    cp_tile32(base + SM_AH(0), Ah, tid);
    cp_tile32(base + SM_AL(0), Al, tid);
    cp_tile32(base + SM_BH(0), Bh, tid);
    cp_tile32(base + SM_BL(0), Bl, tid);
    asm volatile("cp.async.commit_group;" ::: "memory");
    cp_tile32(base + SM_AH(1), Ah + KSTAGE, tid);
    cp_tile32(base + SM_AL(1), Al + KSTAGE, tid);
    cp_tile32(base + SM_BH(1), Bh + KSTAGE, tid);
    cp_tile32(base + SM_BL(1), Bl + KSTAGE, tid);
    asm volatile("cp.async.commit_group;" ::: "memory");

    #pragma unroll 1
    for (int s = 0; s < NSTAGES; s++) {
        const int b = s & 1;
        if (s < NSTAGES - 1)
            asm volatile("cp.async.wait_group 1;" ::: "memory");
        else
            asm volatile("cp.async.wait_group 0;" ::: "memory");
        __syncthreads();

        const uint32_t bAh = base + SM_AH(b);
        const uint32_t bAl = base + SM_AL(b);
        const uint32_t bBh = base + SM_BH(b);
        const uint32_t bBl = base + SM_BL(b);

        // 3 combos: (Ah,Bh), (Ah,Bl), (Al,Bh)
        #pragma unroll
        for (int combo = 0; combo < 3; combo++) {
            const uint32_t ab = (combo == 2) ? bAl : bAh;
            const uint32_t bb = (combo == 1) ? bBl : bBh;
            #pragma unroll
            for (int ks = 0; ks < 2; ks++) {
                uint32_t afr[4][4];
                #pragma unroll
                for (int mi = 0; mi < 4; mi++)
                    ldmatrix_x4(afr[mi], ab + aoff[ks][mi]);
                uint32_t bfr[2][4];
                #pragma unroll
                for (int np = 0; np < 2; np++)
                    ldmatrix_x4(bfr[np], bb + boff[ks][np]);
                #pragma unroll
                for (int mi = 0; mi < 4; mi++)
                    #pragma unroll
                    for (int ni = 0; ni < 4; ni++)
                        mma16816(acc[mi][ni], afr[mi],
                                 bfr[ni >> 1][(ni & 1) * 2],
                                 bfr[ni >> 1][(ni & 1) * 2 + 1]);
            }
        }
        __syncthreads();
        if (s + 2 < NSTAGES) {
            const int k0 = (s + 2) * KSTAGE;
            cp_tile32(base + SM_AH(b), Ah + k0, tid);
            cp_tile32(base + SM_AL(b), Al + k0, tid);
            cp_tile32(base + SM_BH(b), Bh + k0, tid);
            cp_tile32(base + SM_BL(b), Bl + k0, tid);
        }
        asm volatile("cp.async.commit_group;" ::: "memory");
    }

    // ---------------- epilogue: bias + online softmax ----------------
    const int q  = lane >> 2;     // quad id: row within 8
    const int tq = lane & 3;      // col pair selector

    #pragma unroll
    for (int mi = 0; mi < 4; mi++) {
        #pragma unroll
        for (int half = 0; half < 2; half++) {
            float v[8];
            #pragma unroll
            for (int ni = 0; ni < 4; ni++) {
                int col = warp_n * 32 + ni * 8 + tq * 2;
                v[ni * 2 + 0] = acc[mi][ni][half * 2 + 0] + bias_sm[col];
                v[ni * 2 + 1] = acc[mi][ni][half * 2 + 1] + bias_sm[col + 1];
            }
            float M = v[0];
            #pragma unroll
            for (int j = 1; j < 8; j++) M = fmaxf(M, v[j]);
            float S = 0.0f;
            #pragma unroll
            for (int j = 0; j < 8; j++) S += __expf(v[j] - M);
            // merge across the 4 lanes sharing this row (xor 1, 2)
            #pragma unroll
            for (int o = 1; o <= 2; o <<= 1) {
                float oM = __shfl_xor_sync(0xffffffffu, M, o);
                float oS = __shfl_xor_sync(0xffffffffu, S, o);
                float nm = fmaxf(M, oM);
                S = S * __expf(M - nm) + oS * __expf(oM - nm);
                M = nm;
            }
            if (tq == 0) {
                int row = warp_m * 64 + mi * 16 + half * 8 + q;
                redM[warp_n][row] = M;
                redS[warp_n][row] = S;
            }
        }
    }
    __syncthreads();

    if (tid < TILE_M) {
        float M = redM[0][tid], S = redS[0][tid];
        #pragma unroll
        for (int w = 1; w < 4; w++) {
            float oM = redM[w][tid], oS = redS[w][tid];
            float nm = fmaxf(M, oM);
            S = S * __expf(M - nm) + oS * __expf(oM - nm);
            M = nm;
        }
        g_partials[pass][(size_t)blockIdx.y * BT + m0 + tid] = make_float2(M, S);
    }
}

// =================================================================
// Kernel 2: exact fp32 target logits
// =================================================================
__global__ __launch_bounds__(128)
void tgt_logit_kernel(const float* __restrict__ x0, const float* __restrict__ w0,
                      const float* __restrict__ b0,
                      const float* __restrict__ x1, const float* __restrict__ w1,
                      const float* __restrict__ b1, const void* __restrict__ tgt)
{
    const int pass = blockIdx.y;
    const float* X  = pass ? x1 : x0;
    const float* W  = pass ? w1 : w0;
    const float* BV = pass ? b1 : b0;
    const int tok = blockIdx.x;

    const bool is64 = target_is_i64(tgt);
    long long t = load_tgt(tgt, tok, is64);
    int tc = (int)t;
    tc = tc < 0 ? 0 : (tc >= VOCAB ? VOCAB - 1 : tc);

    const float4* xv = (const float4*)(X + (size_t)tok * HDIM);
    const float4* wv = (const float4*)(W + (size_t)tc * HDIM);
    float s = 0.0f;
    for (int c = threadIdx.x; c < HDIM / 4; c += blockDim.x) {
        float4 a = xv[c], b = wv[c];
        s += a.x * b.x + a.y * b.y + a.z * b.z + a.w * b.w;
    }
    #pragma unroll
    for (int o = 16; o; o >>= 1) s += __shfl_xor_sync(0xffffffffu, s, o);
    __shared__ float red[4];
    if ((threadIdx.x & 31) == 0) red[threadIdx.x >> 5] = s;
    __syncthreads();
    if (threadIdx.x == 0)
        g_tgt[pass][tok] = red[0] + red[1] + red[2] + red[3] + BV[tc];
}

// =================================================================
// Kernel 3: combine partials -> per-seq sums
// =================================================================
__global__ __launch_bounds__(256)
void combine_kernel(const void* __restrict__ tgt)
{
    const int b = blockIdx.x;
    const int tid = threadIdx.x;
    const bool is64 = target_is_i64(tgt);
    float accp = 0.0f, accr = 0.0f;

    for (int it = 0; it < TSEQ; it += 256) {
        const int tok = b * TSEQ + it + tid;
        long long t = load_tgt(tgt, tok, is64);
        if (t != IGNORE_INDEX) {
            #pragma unroll
            for (int p = 0; p < 2; p++) {
                float M = -INFINITY, S = 0.0f;
                #pragma unroll 1
                for (int c = 0; c < NTILES_N; c++) {
                    float2 pc = g_partials[p][(size_t)c * BT + tok];
                    float nm = fmaxf(M, pc.x);
                    S = S * __expf(M - nm) + pc.y * __expf(pc.x - nm);
                    M = nm;
                }
                float lp = g_tgt[p][tok] - (M + logf(S));
                if (p == 0) accp += lp; else accr += lp;
            }
        }
    }
    #pragma unroll
    for (int o = 16; o; o >>= 1) {
        accp += __shfl_xor_sync(0xffffffffu, accp, o);
        accr += __shfl_xor_sync(0xffffffffu, accr, o);
    }
    __shared__ float sp[8], sr[8];
    if ((tid & 31) == 0) { sp[tid >> 5] = accp; sr[tid >> 5] = accr; }
    __syncthreads();
    if (tid == 0) {
        float a = 0.0f, r = 0.0f;
        #pragma unroll
        for (int i = 0; i < 8; i++) { a += sp[i]; r += sr[i]; }
        g_seq[0][b] = a;
        g_seq[1][b] = r;
    }
}

// =================================================================
// Kernel 4: final KTO loss
// =================================================================
__global__ void final_kernel(const void* __restrict__ pref,
                             const float* __restrict__ kl,
                             float* __restrict__ out, int out_size)
{
    if (threadIdx.x != 0) return;
    const int* pw = (const int*)pref;
    bool isInt = true;
    int li[BSEQ];
    #pragma unroll
    for (int i = 0; i < BSEQ; i++) {
        int v = pw[i];
        if (v != 0 && v != 1) isInt = false;
        li[i] = v;
    }
    const unsigned char* pb = (const unsigned char*)pref;
    int lab[BSEQ];
    #pragma unroll
    for (int i = 0; i < BSEQ; i++)
        lab[i] = isInt ? li[i] : (pb[i] != 0 ? 1 : 0);

    const float kl0 = kl[0];
    float loss = 0.0f, ch = 0.0f, rj = 0.0f;
    #pragma unroll
    for (int b = 0; b < BSEQ; b++) {
        float lr   = g_seq[0][b] - g_seq[1][b];
        float mult = lab[b] ? 1.0f : -1.0f;
        float z    = BETA * (lr - kl0) * mult;
        loss += 1.0f - 1.0f / (1.0f + expf(-z));
        float rw = BETA * lr;
        if (lab[b]) ch += rw; else rj += rw;
    }
    loss /= (float)BT;
    if (out_size > 0) out[0] = loss;
    if (out_size > 1) out[1] = ch;
    if (out_size > 2) out[2] = rj;
}

// =================================================================
extern "C" void kernel_launch(void* const* d_in, const int* in_sizes, int n_in,
                              void* d_out, int out_size)
{
    const float* x    = (const float*)d_in[0];
    const float* w    = (const float*)d_in[1];
    const void*  tgt  = d_in[2];
    const float* bias = (const float*)d_in[3];
    const void*  pref = d_in[4];
    const float* xr   = (const float*)d_in[5];
    const float* wr   = (const float*)d_in[6];
    const float* br   = (const float*)d_in[7];
    const float* kl   = (const float*)d_in[8];

    __nv_bfloat16 *whi, *wlo, *xhi, *xlo;
    cudaGetSymbolAddress((void**)&whi, g_whi);
    cudaGetSymbolAddress((void**)&wlo, g_wlo);
    cudaGetSymbolAddress((void**)&xhi, g_xhi);
    cudaGetSymbolAddress((void**)&xlo, g_xlo);

    const long long WN4 = (long long)VOCAB * HDIM / 4;
    const long long XN4 = (long long)BT * HDIM / 4;
    split_kernel<<<2048, 256>>>(w,  whi, wlo, WN4);
    split_kernel<<<2048, 256>>>(wr, whi + (size_t)VOCAB * HDIM,
                                     wlo + (size_t)VOCAB * HDIM, WN4);
    split_kernel<<<256, 256>>>(x,  xhi, xlo, XN4);
    split_kernel<<<256, 256>>>(xr, xhi + (size_t)BT * HDIM,
                                    xlo + (size_t)BT * HDIM, XN4);

    cudaFuncSetAttribute(lse_mma_kernel,
                         cudaFuncAttributeMaxDynamicSharedMemorySize, SMEM_DYN);
    dim3 g1(NTILES_M, NTILES_N, 2);
    lse_mma_kernel<<<g1, 256, SMEM_DYN>>>(bias, br);

    tgt_logit_kernel<<<dim3(BT, 2), 128>>>(x, w, bias, xr, wr, br, tgt);
    combine_kernel<<<BSEQ, 256>>>(tgt);
    final_kernel<<<1, 32>>>(pref, kl, (float*)d_out, out_size);
}

// round 4
// speedup vs baseline: 3.5324x; 1.0439x over previous
#include <cuda_runtime.h>
#include <cuda_bf16.h>
#include <math.h>
#include <stdint.h>

// ---------------- problem constants ----------------
#define BT      2048
#define BSEQ    4
#define TSEQ    512
#define HDIM    1024
#define VOCAB   32000
#define IGNORE_INDEX (-100)
#define BETA    0.1f

// GEMM tiling
#define TILE_M   128
#define TILE_N   128
#define KSTAGE   32                  // k elems per stage (64B rows)
#define NSTAGES  (HDIM / KSTAGE)     // 32
#define NTILES_M (BT / TILE_M)       // 16
#define NTILES_N (VOCAB / TILE_N)    // 250

// dynamic smem: 4 stages x 4 tiles x (128 rows x 64B) = 128KB (+align slack)
#define TILE_BYTES   8192u
#define BUF_BYTES    (4u * TILE_BYTES)
#define SM_AH(b)  ((b) * BUF_BYTES + 0u)
#define SM_AL(b)  ((b) * BUF_BYTES + TILE_BYTES)
#define SM_BH(b)  ((b) * BUF_BYTES + 2u * TILE_BYTES)
#define SM_BL(b)  ((b) * BUF_BYTES + 3u * TILE_BYTES)
#define SMEM_DYN  (4u * BUF_BYTES + 1024u)

// ---------------- device scratch (static) ----------------
__device__ __nv_bfloat16 g_whi[2ULL * VOCAB * HDIM];
__device__ __nv_bfloat16 g_wlo[2ULL * VOCAB * HDIM];
__device__ __nv_bfloat16 g_xhi[2ULL * BT * HDIM];
__device__ __nv_bfloat16 g_xlo[2ULL * BT * HDIM];
__device__ float2 g_partials[2][(size_t)NTILES_N * BT];
__device__ float  g_tgt[2][BT];
__device__ float  g_seq[2][BSEQ];

// ---------------- helpers ----------------
__device__ __forceinline__ uint32_t smem_u32(const void* p) {
    uint32_t a;
    asm("{ .reg .u64 t; cvta.to.shared.u64 t, %1; cvt.u32.u64 %0, t; }" : "=r"(a) : "l"(p));
    return a;
}
// SW64 swizzle for 64B rows: XOR 16B-chunk bits[5:4] with row bits (off bits [8:7])
__device__ __forceinline__ uint32_t swz64(uint32_t off) {
    return off ^ ((off >> 3) & 0x30u);
}
__device__ __forceinline__ void ldmatrix_x4(uint32_t* r, uint32_t addr) {
    asm volatile("ldmatrix.sync.aligned.m8n8.x4.shared.b16 {%0,%1,%2,%3}, [%4];"
                 : "=r"(r[0]), "=r"(r[1]), "=r"(r[2]), "=r"(r[3]) : "r"(addr));
}
__device__ __forceinline__ void mma16816(float* d, const uint32_t* a,
                                         uint32_t b0, uint32_t b1) {
    asm volatile("mma.sync.aligned.m16n8k16.row.col.f32.bf16.bf16.f32 "
                 "{%0,%1,%2,%3}, {%4,%5,%6,%7}, {%8,%9}, {%0,%1,%2,%3};"
                 : "+f"(d[0]), "+f"(d[1]), "+f"(d[2]), "+f"(d[3])
                 : "r"(a[0]), "r"(a[1]), "r"(a[2]), "r"(a[3]), "r"(b0), "r"(b1));
}

// ---------------- dtype detection ----------------
__device__ __forceinline__ bool target_is_i64(const void* t) {
    const int* w = (const int*)t;
    bool is64 = true;
    #pragma unroll
    for (int i = 0; i < 32; i++)
        if (w[2 * i + 1] != 0) is64 = false;
    return is64;
}
__device__ __forceinline__ long long load_tgt(const void* t, int i, bool is64) {
    return is64 ? ((const long long*)t)[i] : (long long)((const int*)t)[i];
}

// =================================================================
// Kernel 0: fp32 -> (bf16 hi, bf16 lo) split
// =================================================================
__global__ __launch_bounds__(256)
void split_kernel(const float* __restrict__ src, __nv_bfloat16* __restrict__ hi,
                  __nv_bfloat16* __restrict__ lo, long long n4)
{
    long long stride = (long long)gridDim.x * blockDim.x;
    const float4* s4 = (const float4*)src;
    uint2* h2 = (uint2*)hi;
    uint2* l2 = (uint2*)lo;
    for (long long i = (long long)blockIdx.x * blockDim.x + threadIdx.x; i < n4; i += stride) {
        float4 v = s4[i];
        float f[4] = {v.x, v.y, v.z, v.w};
        unsigned short hs[4], ls[4];
        #pragma unroll
        for (int j = 0; j < 4; j++) {
            __nv_bfloat16 h = __float2bfloat16_rn(f[j]);
            float rem = f[j] - __bfloat162float(h);
            __nv_bfloat16 l = __float2bfloat16_rn(rem);
            hs[j] = __bfloat16_as_ushort(h);
            ls[j] = __bfloat16_as_ushort(l);
        }
        uint2 ho, lu;
        ho.x = (uint32_t)hs[0] | ((uint32_t)hs[1] << 16);
        ho.y = (uint32_t)hs[2] | ((uint32_t)hs[3] << 16);
        lu.x = (uint32_t)ls[0] | ((uint32_t)ls[1] << 16);
        lu.y = (uint32_t)ls[2] | ((uint32_t)ls[3] << 16);
        h2[i] = ho;
        l2[i] = lu;
    }
}

// =================================================================
// Kernel 1: HMMA bf16 hi/lo GEMM + fused online-softmax partials
//   grid (16, 250, 2), block 256 (8 warps: 2m x 4n), warp tile 64x32
//   4-stage cp.async ring, fragments reused across the 3 combos
// =================================================================
__device__ __forceinline__ void cp_tile32(uint32_t dst, const __nv_bfloat16* src,
                                          int tid)
{
    // tile: 128 rows x 32 bf16 (64B rows), SW64-swizzled; 512 x 16B chunks
    #pragma unroll
    for (int i = 0; i < 2; i++) {
        int idx = tid + i * 256;
        int r = idx >> 2;
        int c = idx & 3;
        uint32_t off = (uint32_t)r * 64u + (uint32_t)c * 16u;
        const char* g = (const char*)src + (size_t)r * (HDIM * 2) + c * 16;
        asm volatile("cp.async.cg.shared.global [%0], [%1], 16;"
                     :: "r"(dst + swz64(off)), "l"(g) : "memory");
    }
}

__global__ __launch_bounds__(256, 1)
void lse_mma_kernel(const float* __restrict__ b0v, const float* __restrict__ b1v)
{
    extern __shared__ char dsm[];
    __shared__ float bias_sm[TILE_N];
    __shared__ float redM[4][TILE_M];
    __shared__ float redS[4][TILE_M];

    const int tid  = threadIdx.x;
    const int wid  = tid >> 5;
    const int lane = tid & 31;
    const int warp_m = wid & 1;        // 0..1
    const int warp_n = wid >> 1;       // 0..3

    uint32_t raw  = smem_u32(dsm);
    uint32_t base = (raw + 1023u) & ~1023u;

    const int m0   = blockIdx.x * TILE_M;
    const int n0   = blockIdx.y * TILE_N;
    const int pass = blockIdx.z;
    const float* BV = pass ? b1v : b0v;

    const __nv_bfloat16* Ah = g_xhi + ((size_t)pass * BT + m0) * HDIM;
    const __nv_bfloat16* Al = g_xlo + ((size_t)pass * BT + m0) * HDIM;
    const __nv_bfloat16* Bh = g_whi + ((size_t)pass * VOCAB + n0) * HDIM;
    const __nv_bfloat16* Bl = g_wlo + ((size_t)pass * VOCAB + n0) * HDIM;

    if (tid < TILE_N) bias_sm[tid] = BV[n0 + tid];

    // per-lane ldmatrix offsets (tile-relative, swizzled)
    uint32_t aoff[2][4], boff[2][2];
    #pragma unroll
    for (int ks = 0; ks < 2; ks++) {
        #pragma unroll
        for (int mi = 0; mi < 4; mi++) {
            uint32_t row = (uint32_t)(warp_m * 64 + mi * 16 + (lane & 15));
            uint32_t kb  = (uint32_t)(ks * 32 + (lane >> 4) * 16);
            aoff[ks][mi] = swz64(row * 64u + kb);
        }
        #pragma unroll
        for (int np = 0; np < 2; np++) {
            uint32_t n  = (uint32_t)(warp_n * 32 + np * 16 + ((lane >> 4) & 1) * 8 + (lane & 7));
            uint32_t kb = (uint32_t)(ks * 32 + ((lane >> 3) & 1) * 16);
            boff[ks][np] = swz64(n * 64u + kb);
        }
    }

    float acc[4][4][4];
    #pragma unroll
    for (int mi = 0; mi < 4; mi++)
        #pragma unroll
        for (int ni = 0; ni < 4; ni++)
            #pragma unroll
            for (int j = 0; j < 4; j++) acc[mi][ni][j] = 0.0f;

    // prologue: fill stages 0..2
    #pragma unroll
    for (int p = 0; p < 3; p++) {
        const int k0 = p * KSTAGE;
        cp_tile32(base + SM_AH(p), Ah + k0, tid);
        cp_tile32(base + SM_AL(p), Al + k0, tid);
        cp_tile32(base + SM_BH(p), Bh + k0, tid);
        cp_tile32(base + SM_BL(p), Bl + k0, tid);
        asm volatile("cp.async.commit_group;" ::: "memory");
    }

    #pragma unroll 1
    for (int s = 0; s < NSTAGES; s++) {
        const int b = s & 3;
        asm volatile("cp.async.wait_group 2;" ::: "memory");
        __syncthreads();

        // issue loads for stage s+3 into ring slot (s+3)&3 (== (s-1)&3, already consumed)
        if (s + 3 < NSTAGES) {
            const int k0 = (s + 3) * KSTAGE;
            const int nb = (s + 3) & 3;
            cp_tile32(base + SM_AH(nb), Ah + k0, tid);
            cp_tile32(base + SM_AL(nb), Al + k0, tid);
            cp_tile32(base + SM_BH(nb), Bh + k0, tid);
            cp_tile32(base + SM_BL(nb), Bl + k0, tid);
        }
        asm volatile("cp.async.commit_group;" ::: "memory");

        const uint32_t bAh = base + SM_AH(b);
        const uint32_t bAl = base + SM_AL(b);
        const uint32_t bBh = base + SM_BH(b);
        const uint32_t bBl = base + SM_BL(b);

        #pragma unroll
        for (int ks = 0; ks < 2; ks++) {
            // load all fragments once, reuse across the 3 combos
            uint32_t afh[4][4], afl[4][4];
            #pragma unroll
            for (int mi = 0; mi < 4; mi++) {
                ldmatrix_x4(afh[mi], bAh + aoff[ks][mi]);
                ldmatrix_x4(afl[mi], bAl + aoff[ks][mi]);
            }
            uint32_t bfh[2][4], bfl[2][4];
            #pragma unroll
            for (int np = 0; np < 2; np++) {
                ldmatrix_x4(bfh[np], bBh + boff[ks][np]);
                ldmatrix_x4(bfl[np], bBl + boff[ks][np]);
            }
            // combo 0: Ah*Bh
            #pragma unroll
            for (int mi = 0; mi < 4; mi++)
                #pragma unroll
                for (int ni = 0; ni < 4; ni++)
                    mma16816(acc[mi][ni], afh[mi],
                             bfh[ni >> 1][(ni & 1) * 2], bfh[ni >> 1][(ni & 1) * 2 + 1]);
            // combo 1: Ah*Bl
            #pragma unroll
            for (int mi = 0; mi < 4; mi++)
                #pragma unroll
                for (int ni = 0; ni < 4; ni++)
                    mma16816(acc[mi][ni], afh[mi],
                             bfl[ni >> 1][(ni & 1) * 2], bfl[ni >> 1][(ni & 1) * 2 + 1]);
            // combo 2: Al*Bh
            #pragma unroll
            for (int mi = 0; mi < 4; mi++)
                #pragma unroll
                for (int ni = 0; ni < 4; ni++)
                    mma16816(acc[mi][ni], afl[mi],
                             bfh[ni >> 1][(ni & 1) * 2], bfh[ni >> 1][(ni & 1) * 2 + 1]);
        }
    }

    // ---------------- epilogue: bias + online softmax ----------------
    const int q  = lane >> 2;     // row within 8
    const int tq = lane & 3;      // col pair selector

    #pragma unroll
    for (int mi = 0; mi < 4; mi++) {
        #pragma unroll
        for (int half = 0; half < 2; half++) {
            float v[8];
            #pragma unroll
            for (int ni = 0; ni < 4; ni++) {
                int col = warp_n * 32 + ni * 8 + tq * 2;
                v[ni * 2 + 0] = acc[mi][ni][half * 2 + 0] + bias_sm[col];
                v[ni * 2 + 1] = acc[mi][ni][half * 2 + 1] + bias_sm[col + 1];
            }
            float M = v[0];
            #pragma unroll
            for (int j = 1; j < 8; j++) M = fmaxf(M, v[j]);
            float S = 0.0f;
            #pragma unroll
            for (int j = 0; j < 8; j++) S += __expf(v[j] - M);
            #pragma unroll
            for (int o = 1; o <= 2; o <<= 1) {
                float oM = __shfl_xor_sync(0xffffffffu, M, o);
                float oS = __shfl_xor_sync(0xffffffffu, S, o);
                float nm = fmaxf(M, oM);
                S = S * __expf(M - nm) + oS * __expf(oM - nm);
                M = nm;
            }
            if (tq == 0) {
                int row = warp_m * 64 + mi * 16 + half * 8 + q;
                redM[warp_n][row] = M;
                redS[warp_n][row] = S;
            }
        }
    }
    __syncthreads();

    if (tid < TILE_M) {
        float M = redM[0][tid], S = redS[0][tid];
        #pragma unroll
        for (int w = 1; w < 4; w++) {
            float oM = redM[w][tid], oS = redS[w][tid];
            float nm = fmaxf(M, oM);
            S = S * __expf(M - nm) + oS * __expf(oM - nm);
            M = nm;
        }
        g_partials[pass][(size_t)blockIdx.y * BT + m0 + tid] = make_float2(M, S);
    }
}

// =================================================================
// Kernel 2: exact fp32 target logits
// =================================================================
__global__ __launch_bounds__(128)
void tgt_logit_kernel(const float* __restrict__ x0, const float* __restrict__ w0,
                      const float* __restrict__ b0,
                      const float* __restrict__ x1, const float* __restrict__ w1,
                      const float* __restrict__ b1, const void* __restrict__ tgt)
{
    const int pass = blockIdx.y;
    const float* X  = pass ? x1 : x0;
    const float* W  = pass ? w1 : w0;
    const float* BV = pass ? b1 : b0;
    const int tok = blockIdx.x;

    const bool is64 = target_is_i64(tgt);
    long long t = load_tgt(tgt, tok, is64);
    int tc = (int)t;
    tc = tc < 0 ? 0 : (tc >= VOCAB ? VOCAB - 1 : tc);

    const float4* xv = (const float4*)(X + (size_t)tok * HDIM);
    const float4* wv = (const float4*)(W + (size_t)tc * HDIM);
    float s = 0.0f;
    for (int c = threadIdx.x; c < HDIM / 4; c += blockDim.x) {
        float4 a = xv[c], b = wv[c];
        s += a.x * b.x + a.y * b.y + a.z * b.z + a.w * b.w;
    }
    #pragma unroll
    for (int o = 16; o; o >>= 1) s += __shfl_xor_sync(0xffffffffu, s, o);
    __shared__ float red[4];
    if ((threadIdx.x & 31) == 0) red[threadIdx.x >> 5] = s;
    __syncthreads();
    if (threadIdx.x == 0)
        g_tgt[pass][tok] = red[0] + red[1] + red[2] + red[3] + BV[tc];
}

// =================================================================
// Kernel 3: combine partials -> per-seq sums
// =================================================================
__global__ __launch_bounds__(256)
void combine_kernel(const void* __restrict__ tgt)
{
    const int b = blockIdx.x;
    const int tid = threadIdx.x;
    const bool is64 = target_is_i64(tgt);
    float accp = 0.0f, accr = 0.0f;

    for (int it = 0; it < TSEQ; it += 256) {
        const int tok = b * TSEQ + it + tid;
        long long t = load_tgt(tgt, tok, is64);
        if (t != IGNORE_INDEX) {
            #pragma unroll
            for (int p = 0; p < 2; p++) {
                float M = -INFINITY, S = 0.0f;
                #pragma unroll 1
                for (int c = 0; c < NTILES_N; c++) {
                    float2 pc = g_partials[p][(size_t)c * BT + tok];
                    float nm = fmaxf(M, pc.x);
                    S = S * __expf(M - nm) + pc.y * __expf(pc.x - nm);
                    M = nm;
                }
                float lp = g_tgt[p][tok] - (M + logf(S));
                if (p == 0) accp += lp; else accr += lp;
            }
        }
    }
    #pragma unroll
    for (int o = 16; o; o >>= 1) {
        accp += __shfl_xor_sync(0xffffffffu, accp, o);
        accr += __shfl_xor_sync(0xffffffffu, accr, o);
    }
    __shared__ float sp[8], sr[8];
    if ((tid & 31) == 0) { sp[tid >> 5] = accp; sr[tid >> 5] = accr; }
    __syncthreads();
    if (tid == 0) {
        float a = 0.0f, r = 0.0f;
        #pragma unroll
        for (int i = 0; i < 8; i++) { a += sp[i]; r += sr[i]; }
        g_seq[0][b] = a;
        g_seq[1][b] = r;
    }
}

// =================================================================
// Kernel 4: final KTO loss
// =================================================================
__global__ void final_kernel(const void* __restrict__ pref,
                             const float* __restrict__ kl,
                             float* __restrict__ out, int out_size)
{
    if (threadIdx.x != 0) return;
    const int* pw = (const int*)pref;
    bool isInt = true;
    int li[BSEQ];
    #pragma unroll
    for (int i = 0; i < BSEQ; i++) {
        int v = pw[i];
        if (v != 0 && v != 1) isInt = false;
        li[i] = v;
    }
    const unsigned char* pb = (const unsigned char*)pref;
    int lab[BSEQ];
    #pragma unroll
    for (int i = 0; i < BSEQ; i++)
        lab[i] = isInt ? li[i] : (pb[i] != 0 ? 1 : 0);

    const float kl0 = kl[0];
    float loss = 0.0f, ch = 0.0f, rj = 0.0f;
    #pragma unroll
    for (int b = 0; b < BSEQ; b++) {
        float lr   = g_seq[0][b] - g_seq[1][b];
        float mult = lab[b] ? 1.0f : -1.0f;
        float z    = BETA * (lr - kl0) * mult;
        loss += 1.0f - 1.0f / (1.0f + expf(-z));
        float rw = BETA * lr;
        if (lab[b]) ch += rw; else rj += rw;
    }
    loss /= (float)BT;
    if (out_size > 0) out[0] = loss;
    if (out_size > 1) out[1] = ch;
    if (out_size > 2) out[2] = rj;
}

// =================================================================
extern "C" void kernel_launch(void* const* d_in, const int* in_sizes, int n_in,
                              void* d_out, int out_size)
{
    const float* x    = (const float*)d_in[0];
    const float* w    = (const float*)d_in[1];
    const void*  tgt  = d_in[2];
    const float* bias = (const float*)d_in[3];
    const void*  pref = d_in[4];
    const float* xr   = (const float*)d_in[5];
    const float* wr   = (const float*)d_in[6];
    const float* br   = (const float*)d_in[7];
    const float* kl   = (const float*)d_in[8];

    __nv_bfloat16 *whi, *wlo, *xhi, *xlo;
    cudaGetSymbolAddress((void**)&whi, g_whi);
    cudaGetSymbolAddress((void**)&wlo, g_wlo);
    cudaGetSymbolAddress((void**)&xhi, g_xhi);
    cudaGetSymbolAddress((void**)&xlo, g_xlo);

    const long long WN4 = (long long)VOCAB * HDIM / 4;
    const long long XN4 = (long long)BT * HDIM / 4;
    split_kernel<<<2048, 256>>>(w,  whi, wlo, WN4);
    split_kernel<<<2048, 256>>>(wr, whi + (size_t)VOCAB * HDIM,
                                     wlo + (size_t)VOCAB * HDIM, WN4);
    split_kernel<<<256, 256>>>(x,  xhi, xlo, XN4);
    split_kernel<<<256, 256>>>(xr, xhi + (size_t)BT * HDIM,
                                    xlo + (size_t)BT * HDIM, XN4);

    cudaFuncSetAttribute(lse_mma_kernel,
                         cudaFuncAttributeMaxDynamicSharedMemorySize, SMEM_DYN);
    dim3 g1(NTILES_M, NTILES_N, 2);
    lse_mma_kernel<<<g1, 256, SMEM_DYN>>>(bias, br);

    tgt_logit_kernel<<<dim3(BT, 2), 128>>>(x, w, bias, xr, wr, br, tgt);
    combine_kernel<<<BSEQ, 256>>>(tgt);
    final_kernel<<<1, 32>>>(pref, kl, (float*)d_out, out_size);
}

// round 5
// speedup vs baseline: 3.5341x; 1.0005x over previous
#include <cuda_runtime.h>
#include <cuda_bf16.h>
#include <math.h>
#include <stdint.h>

// ---------------- problem constants ----------------
#define BT      2048
#define BSEQ    4
#define TSEQ    512
#define HDIM    1024
#define VOCAB   32000
#define IGNORE_INDEX (-100)
#define BETA    0.1f

// GEMM tiling
#define TILE_M   128
#define TILE_N   128
#define KSTAGE   32                  // k elems per stage (64B rows)
#define NSTAGES  (HDIM / KSTAGE)     // 32
#define NTILES_M (BT / TILE_M)       // 16
#define NTILES_N (VOCAB / TILE_N)    // 250

// dynamic smem: 4 stages x 4 tiles x (128 rows x 64B) = 128KB (+align slack)
#define TILE_BYTES   8192u
#define BUF_BYTES    (4u * TILE_BYTES)
#define SM_AH(b)  ((b) * BUF_BYTES + 0u)
#define SM_AL(b)  ((b) * BUF_BYTES + TILE_BYTES)
#define SM_BH(b)  ((b) * BUF_BYTES + 2u * TILE_BYTES)
#define SM_BL(b)  ((b) * BUF_BYTES + 3u * TILE_BYTES)
#define SMEM_DYN  (4u * BUF_BYTES + 1024u)

// ---------------- device scratch (static) ----------------
__device__ __nv_bfloat16 g_whi[2ULL * VOCAB * HDIM];
__device__ __nv_bfloat16 g_wlo[2ULL * VOCAB * HDIM];
__device__ __nv_bfloat16 g_xhi[2ULL * BT * HDIM];
__device__ __nv_bfloat16 g_xlo[2ULL * BT * HDIM];
__device__ float2 g_partials[2][(size_t)NTILES_N * BT];
__device__ float  g_tgt[2][BT];
__device__ float  g_seq[2][BSEQ];

// ---------------- helpers ----------------
__device__ __forceinline__ uint32_t smem_u32(const void* p) {
    uint32_t a;
    asm("{ .reg .u64 t; cvta.to.shared.u64 t, %1; cvt.u32.u64 %0, t; }" : "=r"(a) : "l"(p));
    return a;
}
// SW64 swizzle for 64B rows: XOR 16B-chunk bits[5:4] with row bits (off bits [8:7])
__device__ __forceinline__ uint32_t swz64(uint32_t off) {
    return off ^ ((off >> 3) & 0x30u);
}
__device__ __forceinline__ void ldmatrix_x4(uint32_t* r, uint32_t addr) {
    asm volatile("ldmatrix.sync.aligned.m8n8.x4.shared.b16 {%0,%1,%2,%3}, [%4];"
                 : "=r"(r[0]), "=r"(r[1]), "=r"(r[2]), "=r"(r[3]) : "r"(addr));
}
__device__ __forceinline__ void mma16816(float* d, const uint32_t* a,
                                         uint32_t b0, uint32_t b1) {
    asm volatile("mma.sync.aligned.m16n8k16.row.col.f32.bf16.bf16.f32 "
                 "{%0,%1,%2,%3}, {%4,%5,%6,%7}, {%8,%9}, {%0,%1,%2,%3};"
                 : "+f"(d[0]), "+f"(d[1]), "+f"(d[2]), "+f"(d[3])
                 : "r"(a[0]), "r"(a[1]), "r"(a[2]), "r"(a[3]), "r"(b0), "r"(b1));
}

// ---------------- dtype detection ----------------
__device__ __forceinline__ bool target_is_i64(const void* t) {
    const int* w = (const int*)t;
    bool is64 = true;
    #pragma unroll
    for (int i = 0; i < 32; i++)
        if (w[2 * i + 1] != 0) is64 = false;
    return is64;
}
__device__ __forceinline__ long long load_tgt(const void* t, int i, bool is64) {
    return is64 ? ((const long long*)t)[i] : (long long)((const int*)t)[i];
}

// =================================================================
// Kernel 0: fp32 -> (bf16 hi, bf16 lo) split
// =================================================================
__global__ __launch_bounds__(256)
void split_kernel(const float* __restrict__ src, __nv_bfloat16* __restrict__ hi,
                  __nv_bfloat16* __restrict__ lo, long long n4)
{
    long long stride = (long long)gridDim.x * blockDim.x;
    const float4* s4 = (const float4*)src;
    uint2* h2 = (uint2*)hi;
    uint2* l2 = (uint2*)lo;
    for (long long i = (long long)blockIdx.x * blockDim.x + threadIdx.x; i < n4; i += stride) {
        float4 v = s4[i];
        float f[4] = {v.x, v.y, v.z, v.w};
        unsigned short hs[4], ls[4];
        #pragma unroll
        for (int j = 0; j < 4; j++) {
            __nv_bfloat16 h = __float2bfloat16_rn(f[j]);
            float rem = f[j] - __bfloat162float(h);
            __nv_bfloat16 l = __float2bfloat16_rn(rem);
            hs[j] = __bfloat16_as_ushort(h);
            ls[j] = __bfloat16_as_ushort(l);
        }
        uint2 ho, lu;
        ho.x = (uint32_t)hs[0] | ((uint32_t)hs[1] << 16);
        ho.y = (uint32_t)hs[2] | ((uint32_t)hs[3] << 16);
        lu.x = (uint32_t)ls[0] | ((uint32_t)ls[1] << 16);
        lu.y = (uint32_t)ls[2] | ((uint32_t)ls[3] << 16);
        h2[i] = ho;
        l2[i] = lu;
    }
}

// =================================================================
// Kernel 1: HMMA bf16 hi/lo GEMM + fused online-softmax partials
//   grid (16, 250, 2), block 256 (8 warps: 2m x 4n), warp tile 64x32
//   4-stage cp.async ring, fragments reused across the 3 combos
// =================================================================
__device__ __forceinline__ void cp_tile32(uint32_t dst, const __nv_bfloat16* src,
                                          int tid)
{
    // tile: 128 rows x 32 bf16 (64B rows), SW64-swizzled; 512 x 16B chunks
    #pragma unroll
    for (int i = 0; i < 2; i++) {
        int idx = tid + i * 256;
        int r = idx >> 2;
        int c = idx & 3;
        uint32_t off = (uint32_t)r * 64u + (uint32_t)c * 16u;
        const char* g = (const char*)src + (size_t)r * (HDIM * 2) + c * 16;
        asm volatile("cp.async.cg.shared.global [%0], [%1], 16;"
                     :: "r"(dst + swz64(off)), "l"(g) : "memory");
    }
}

__global__ __launch_bounds__(256, 1)
void lse_mma_kernel(const float* __restrict__ b0v, const float* __restrict__ b1v)
{
    extern __shared__ char dsm[];
    __shared__ float bias_sm[TILE_N];
    __shared__ float redM[4][TILE_M];
    __shared__ float redS[4][TILE_M];

    const int tid  = threadIdx.x;
    const int wid  = tid >> 5;
    const int lane = tid & 31;
    const int warp_m = wid & 1;        // 0..1
    const int warp_n = wid >> 1;       // 0..3

    uint32_t raw  = smem_u32(dsm);
    uint32_t base = (raw + 1023u) & ~1023u;

    const int m0   = blockIdx.x * TILE_M;
    const int n0   = blockIdx.y * TILE_N;
    const int pass = blockIdx.z;
    const float* BV = pass ? b1v : b0v;

    const __nv_bfloat16* Ah = g_xhi + ((size_t)pass * BT + m0) * HDIM;
    const __nv_bfloat16* Al = g_xlo + ((size_t)pass * BT + m0) * HDIM;
    const __nv_bfloat16* Bh = g_whi + ((size_t)pass * VOCAB + n0) * HDIM;
    const __nv_bfloat16* Bl = g_wlo + ((size_t)pass * VOCAB + n0) * HDIM;

    if (tid < TILE_N) bias_sm[tid] = BV[n0 + tid];

    // per-lane ldmatrix offsets (tile-relative, swizzled)
    uint32_t aoff[2][4], boff[2][2];
    #pragma unroll
    for (int ks = 0; ks < 2; ks++) {
        #pragma unroll
        for (int mi = 0; mi < 4; mi++) {
            uint32_t row = (uint32_t)(warp_m * 64 + mi * 16 + (lane & 15));
            uint32_t kb  = (uint32_t)(ks * 32 + (lane >> 4) * 16);
            aoff[ks][mi] = swz64(row * 64u + kb);
        }
        #pragma unroll
        for (int np = 0; np < 2; np++) {
            uint32_t n  = (uint32_t)(warp_n * 32 + np * 16 + ((lane >> 4) & 1) * 8 + (lane & 7));
            uint32_t kb = (uint32_t)(ks * 32 + ((lane >> 3) & 1) * 16);
            boff[ks][np] = swz64(n * 64u + kb);
        }
    }

    float acc[4][4][4];
    #pragma unroll
    for (int mi = 0; mi < 4; mi++)
        #pragma unroll
        for (int ni = 0; ni < 4; ni++)
            #pragma unroll
            for (int j = 0; j < 4; j++) acc[mi][ni][j] = 0.0f;

    // prologue: fill stages 0..2
    #pragma unroll
    for (int p = 0; p < 3; p++) {
        const int k0 = p * KSTAGE;
        cp_tile32(base + SM_AH(p), Ah + k0, tid);
        cp_tile32(base + SM_AL(p), Al + k0, tid);
        cp_tile32(base + SM_BH(p), Bh + k0, tid);
        cp_tile32(base + SM_BL(p), Bl + k0, tid);
        asm volatile("cp.async.commit_group;" ::: "memory");
    }

    #pragma unroll 1
    for (int s = 0; s < NSTAGES; s++) {
        const int b = s & 3;
        asm volatile("cp.async.wait_group 2;" ::: "memory");
        __syncthreads();

        // issue loads for stage s+3 into ring slot (s+3)&3 (== (s-1)&3, already consumed)
        if (s + 3 < NSTAGES) {
            const int k0 = (s + 3) * KSTAGE;
            const int nb = (s + 3) & 3;
            cp_tile32(base + SM_AH(nb), Ah + k0, tid);
            cp_tile32(base + SM_AL(nb), Al + k0, tid);
            cp_tile32(base + SM_BH(nb), Bh + k0, tid);
            cp_tile32(base + SM_BL(nb), Bl + k0, tid);
        }
        asm volatile("cp.async.commit_group;" ::: "memory");

        const uint32_t bAh = base + SM_AH(b);
        const uint32_t bAl = base + SM_AL(b);
        const uint32_t bBh = base + SM_BH(b);
        const uint32_t bBl = base + SM_BL(b);

        #pragma unroll
        for (int ks = 0; ks < 2; ks++) {
            // load all fragments once, reuse across the 3 combos
            uint32_t afh[4][4], afl[4][4];
            #pragma unroll
            for (int mi = 0; mi < 4; mi++) {
                ldmatrix_x4(afh[mi], bAh + aoff[ks][mi]);
                ldmatrix_x4(afl[mi], bAl + aoff[ks][mi]);
            }
            uint32_t bfh[2][4], bfl[2][4];
            #pragma unroll
            for (int np = 0; np < 2; np++) {
                ldmatrix_x4(bfh[np], bBh + boff[ks][np]);
                ldmatrix_x4(bfl[np], bBl + boff[ks][np]);
            }
            // combo 0: Ah*Bh
            #pragma unroll
            for (int mi = 0; mi < 4; mi++)
                #pragma unroll
                for (int ni = 0; ni < 4; ni++)
                    mma16816(acc[mi][ni], afh[mi],
                             bfh[ni >> 1][(ni & 1) * 2], bfh[ni >> 1][(ni & 1) * 2 + 1]);
            // combo 1: Ah*Bl
            #pragma unroll
            for (int mi = 0; mi < 4; mi++)
                #pragma unroll
                for (int ni = 0; ni < 4; ni++)
                    mma16816(acc[mi][ni], afh[mi],
                             bfl[ni >> 1][(ni & 1) * 2], bfl[ni >> 1][(ni & 1) * 2 + 1]);
            // combo 2: Al*Bh
            #pragma unroll
            for (int mi = 0; mi < 4; mi++)
                #pragma unroll
                for (int ni = 0; ni < 4; ni++)
                    mma16816(acc[mi][ni], afl[mi],
                             bfh[ni >> 1][(ni & 1) * 2], bfh[ni >> 1][(ni & 1) * 2 + 1]);
        }
    }

    // ---------------- epilogue: bias + online softmax ----------------
    const int q  = lane >> 2;     // row within 8
    const int tq = lane & 3;      // col pair selector

    #pragma unroll
    for (int mi = 0; mi < 4; mi++) {
        #pragma unroll
        for (int half = 0; half < 2; half++) {
            float v[8];
            #pragma unroll
            for (int ni = 0; ni < 4; ni++) {
                int col = warp_n * 32 + ni * 8 + tq * 2;
                v[ni * 2 + 0] = acc[mi][ni][half * 2 + 0] + bias_sm[col];
                v[ni * 2 + 1] = acc[mi][ni][half * 2 + 1] + bias_sm[col + 1];
            }
            float M = v[0];
            #pragma unroll
            for (int j = 1; j < 8; j++) M = fmaxf(M, v[j]);
            float S = 0.0f;
            #pragma unroll
            for (int j = 0; j < 8; j++) S += __expf(v[j] - M);
            #pragma unroll
            for (int o = 1; o <= 2; o <<= 1) {
                float oM = __shfl_xor_sync(0xffffffffu, M, o);
                float oS = __shfl_xor_sync(0xffffffffu, S, o);
                float nm = fmaxf(M, oM);
                S = S * __expf(M - nm) + oS * __expf(oM - nm);
                M = nm;
            }
            if (tq == 0) {
                int row = warp_m * 64 + mi * 16 + half * 8 + q;
                redM[warp_n][row] = M;
                redS[warp_n][row] = S;
            }
        }
    }
    __syncthreads();

    if (tid < TILE_M) {
        float M = redM[0][tid], S = redS[0][tid];
        #pragma unroll
        for (int w = 1; w < 4; w++) {
            float oM = redM[w][tid], oS = redS[w][tid];
            float nm = fmaxf(M, oM);
            S = S * __expf(M - nm) + oS * __expf(oM - nm);
            M = nm;
        }
        g_partials[pass][(size_t)blockIdx.y * BT + m0 + tid] = make_float2(M, S);
    }
}

// =================================================================
// Kernel 2: exact fp32 target logits
// =================================================================
__global__ __launch_bounds__(128)
void tgt_logit_kernel(const float* __restrict__ x0, const float* __restrict__ w0,
                      const float* __restrict__ b0,
                      const float* __restrict__ x1, const float* __restrict__ w1,
                      const float* __restrict__ b1, const void* __restrict__ tgt)
{
    const int pass = blockIdx.y;
    const float* X  = pass ? x1 : x0;
    const float* W  = pass ? w1 : w0;
    const float* BV = pass ? b1 : b0;
    const int tok = blockIdx.x;

    const bool is64 = target_is_i64(tgt);
    long long t = load_tgt(tgt, tok, is64);
    int tc = (int)t;
    tc = tc < 0 ? 0 : (tc >= VOCAB ? VOCAB - 1 : tc);

    const float4* xv = (const float4*)(X + (size_t)tok * HDIM);
    const float4* wv = (const float4*)(W + (size_t)tc * HDIM);
    float s = 0.0f;
    for (int c = threadIdx.x; c < HDIM / 4; c += blockDim.x) {
        float4 a = xv[c], b = wv[c];
        s += a.x * b.x + a.y * b.y + a.z * b.z + a.w * b.w;
    }
    #pragma unroll
    for (int o = 16; o; o >>= 1) s += __shfl_xor_sync(0xffffffffu, s, o);
    __shared__ float red[4];
    if ((threadIdx.x & 31) == 0) red[threadIdx.x >> 5] = s;
    __syncthreads();
    if (threadIdx.x == 0)
        g_tgt[pass][tok] = red[0] + red[1] + red[2] + red[3] + BV[tc];
}

// =================================================================
// Kernel 3: combine partials -> per-seq sums
// =================================================================
__global__ __launch_bounds__(256)
void combine_kernel(const void* __restrict__ tgt)
{
    const int b = blockIdx.x;
    const int tid = threadIdx.x;
    const bool is64 = target_is_i64(tgt);
    float accp = 0.0f, accr = 0.0f;

    for (int it = 0; it < TSEQ; it += 256) {
        const int tok = b * TSEQ + it + tid;
        long long t = load_tgt(tgt, tok, is64);
        if (t != IGNORE_INDEX) {
            #pragma unroll
            for (int p = 0; p < 2; p++) {
                float M = -INFINITY, S = 0.0f;
                #pragma unroll 1
                for (int c = 0; c < NTILES_N; c++) {
                    float2 pc = g_partials[p][(size_t)c * BT + tok];
                    float nm = fmaxf(M, pc.x);
                    S = S * __expf(M - nm) + pc.y * __expf(pc.x - nm);
                    M = nm;
                }
                float lp = g_tgt[p][tok] - (M + logf(S));
                if (p == 0) accp += lp; else accr += lp;
            }
        }
    }
    #pragma unroll
    for (int o = 16; o; o >>= 1) {
        accp += __shfl_xor_sync(0xffffffffu, accp, o);
        accr += __shfl_xor_sync(0xffffffffu, accr, o);
    }
    __shared__ float sp[8], sr[8];
    if ((tid & 31) == 0) { sp[tid >> 5] = accp; sr[tid >> 5] = accr; }
    __syncthreads();
    if (tid == 0) {
        float a = 0.0f, r = 0.0f;
        #pragma unroll
        for (int i = 0; i < 8; i++) { a += sp[i]; r += sr[i]; }
        g_seq[0][b] = a;
        g_seq[1][b] = r;
    }
}

// =================================================================
// Kernel 4: final KTO loss
// =================================================================
__global__ void final_kernel(const void* __restrict__ pref,
                             const float* __restrict__ kl,
                             float* __restrict__ out, int out_size)
{
    if (threadIdx.x != 0) return;
    const int* pw = (const int*)pref;
    bool isInt = true;
    int li[BSEQ];
    #pragma unroll
    for (int i = 0; i < BSEQ; i++) {
        int v = pw[i];
        if (v != 0 && v != 1) isInt = false;
        li[i] = v;
    }
    const unsigned char* pb = (const unsigned char*)pref;
    int lab[BSEQ];
    #pragma unroll
    for (int i = 0; i < BSEQ; i++)
        lab[i] = isInt ? li[i] : (pb[i] != 0 ? 1 : 0);

    const float kl0 = kl[0];
    float loss = 0.0f, ch = 0.0f, rj = 0.0f;
    #pragma unroll
    for (int b = 0; b < BSEQ; b++) {
        float lr   = g_seq[0][b] - g_seq[1][b];
        float mult = lab[b] ? 1.0f : -1.0f;
        float z    = BETA * (lr - kl0) * mult;
        loss += 1.0f - 1.0f / (1.0f + expf(-z));
        float rw = BETA * lr;
        if (lab[b]) ch += rw; else rj += rw;
    }
    loss /= (float)BT;
    if (out_size > 0) out[0] = loss;
    if (out_size > 1) out[1] = ch;
    if (out_size > 2) out[2] = rj;
}

// =================================================================
extern "C" void kernel_launch(void* const* d_in, const int* in_sizes, int n_in,
                              void* d_out, int out_size)
{
    const float* x    = (const float*)d_in[0];
    const float* w    = (const float*)d_in[1];
    const void*  tgt  = d_in[2];
    const float* bias = (const float*)d_in[3];
    const void*  pref = d_in[4];
    const float* xr   = (const float*)d_in[5];
    const float* wr   = (const float*)d_in[6];
    const float* br   = (const float*)d_in[7];
    const float* kl   = (const float*)d_in[8];

    __nv_bfloat16 *whi, *wlo, *xhi, *xlo;
    cudaGetSymbolAddress((void**)&whi, g_whi);
    cudaGetSymbolAddress((void**)&wlo, g_wlo);
    cudaGetSymbolAddress((void**)&xhi, g_xhi);
    cudaGetSymbolAddress((void**)&xlo, g_xlo);

    const long long WN4 = (long long)VOCAB * HDIM / 4;
    const long long XN4 = (long long)BT * HDIM / 4;
    split_kernel<<<2048, 256>>>(w,  whi, wlo, WN4);
    split_kernel<<<2048, 256>>>(wr, whi + (size_t)VOCAB * HDIM,
                                     wlo + (size_t)VOCAB * HDIM, WN4);
    split_kernel<<<256, 256>>>(x,  xhi, xlo, XN4);
    split_kernel<<<256, 256>>>(xr, xhi + (size_t)BT * HDIM,
                                    xlo + (size_t)BT * HDIM, XN4);

    cudaFuncSetAttribute(lse_mma_kernel,
                         cudaFuncAttributeMaxDynamicSharedMemorySize, SMEM_DYN);
    dim3 g1(NTILES_M, NTILES_N, 2);
    lse_mma_kernel<<<g1, 256, SMEM_DYN>>>(bias, br);

    tgt_logit_kernel<<<dim3(BT, 2), 128>>>(x, w, bias, xr, wr, br, tgt);
    combine_kernel<<<BSEQ, 256>>>(tgt);
    final_kernel<<<1, 32>>>(pref, kl, (float*)d_out, out_size);
}

// round 9
// speedup vs baseline: 3.9940x; 1.1301x over previous
#include <cuda_runtime.h>
#include <cuda_bf16.h>
#include <math.h>
#include <stdint.h>

// ---------------- problem constants ----------------
#define BT      2048
#define BSEQ    4
#define TSEQ    512
#define HDIM    1024
#define VOCAB   32000
#define IGNORE_INDEX (-100)
#define BETA    0.1f

// GEMM tiling
#define TILE_M   128
#define TILE_N   256
#define KSTAGE   32                  // k elems per stage (64B rows)
#define NSTAGES  (HDIM / KSTAGE)     // 32
#define NTILES_M (BT / TILE_M)       // 16
#define NTILES_N (VOCAB / TILE_N)    // 125
#define NTHREADS 512

// smem: 4 stages x (A hi/lo 8KB each + B hi/lo 16KB each) = 4 x 48KB
#define A_TILE_B  8192u
#define B_TILE_B  16384u
#define STAGE_B   (2u * A_TILE_B + 2u * B_TILE_B)   // 49152
#define SM_AH(b)  ((b) * STAGE_B + 0u)
#define SM_AL(b)  ((b) * STAGE_B + A_TILE_B)
#define SM_BH(b)  ((b) * STAGE_B + 2u * A_TILE_B)
#define SM_BL(b)  ((b) * STAGE_B + 2u * A_TILE_B + B_TILE_B)
#define SMEM_DYN  (4u * STAGE_B + 1024u)            // + align slack

// ---------------- device scratch (static) ----------------
__device__ __nv_bfloat16 g_whi[2ULL * VOCAB * HDIM];
__device__ __nv_bfloat16 g_wlo[2ULL * VOCAB * HDIM];
__device__ __nv_bfloat16 g_xhi[2ULL * BT * HDIM];
__device__ __nv_bfloat16 g_xlo[2ULL * BT * HDIM];
__device__ float2 g_partials[2][(size_t)NTILES_N * BT];
__device__ float  g_tgt[2][BT];
__device__ float  g_seq[2][BSEQ];

// ---------------- helpers ----------------
__device__ __forceinline__ uint32_t smem_u32(const void* p) {
    uint32_t a;
    asm("{ .reg .u64 t; cvta.to.shared.u64 t, %1; cvt.u32.u64 %0, t; }" : "=r"(a) : "l"(p));
    return a;
}
// SW64 swizzle for 64B rows: XOR 16B-chunk bits[5:4] with row bits (off bits [8:7])
__device__ __forceinline__ uint32_t swz64(uint32_t off) {
    return off ^ ((off >> 3) & 0x30u);
}
__device__ __forceinline__ void ldmatrix_x4(uint32_t* r, uint32_t addr) {
    asm volatile("ldmatrix.sync.aligned.m8n8.x4.shared.b16 {%0,%1,%2,%3}, [%4];"
                 : "=r"(r[0]), "=r"(r[1]), "=r"(r[2]), "=r"(r[3]) : "r"(addr));
}
__device__ __forceinline__ void mma16816(float* d, const uint32_t* a,
                                         uint32_t b0, uint32_t b1) {
    asm volatile("mma.sync.aligned.m16n8k16.row.col.f32.bf16.bf16.f32 "
                 "{%0,%1,%2,%3}, {%4,%5,%6,%7}, {%8,%9}, {%0,%1,%2,%3};"
                 : "+f"(d[0]), "+f"(d[1]), "+f"(d[2]), "+f"(d[3])
                 : "r"(a[0]), "r"(a[1]), "r"(a[2]), "r"(a[3]), "r"(b0), "r"(b1));
}

// ---------------- dtype detection ----------------
__device__ __forceinline__ bool target_is_i64(const void* t) {
    const int* w = (const int*)t;
    bool is64 = true;
    #pragma unroll
    for (int i = 0; i < 32; i++)
        if (w[2 * i + 1] != 0) is64 = false;
    return is64;
}
__device__ __forceinline__ long long load_tgt(const void* t, int i, bool is64) {
    return is64 ? ((const long long*)t)[i] : (long long)((const int*)t)[i];
}

// =================================================================
// Kernel 0: fp32 -> (bf16 hi, bf16 lo) split
// =================================================================
__global__ __launch_bounds__(256)
void split_kernel(const float* __restrict__ src, __nv_bfloat16* __restrict__ hi,
                  __nv_bfloat16* __restrict__ lo, long long n4)
{
    long long stride = (long long)gridDim.x * blockDim.x;
    const float4* s4 = (const float4*)src;
    uint2* h2 = (uint2*)hi;
    uint2* l2 = (uint2*)lo;
    for (long long i = (long long)blockIdx.x * blockDim.x + threadIdx.x; i < n4; i += stride) {
        float4 v = s4[i];
        float f[4] = {v.x, v.y, v.z, v.w};
        unsigned short hs[4], ls[4];
        #pragma unroll
        for (int j = 0; j < 4; j++) {
            __nv_bfloat16 h = __float2bfloat16_rn(f[j]);
            float rem = f[j] - __bfloat162float(h);
            __nv_bfloat16 l = __float2bfloat16_rn(rem);
            hs[j] = __bfloat16_as_ushort(h);
            ls[j] = __bfloat16_as_ushort(l);
        }
        uint2 ho, lu;
        ho.x = (uint32_t)hs[0] | ((uint32_t)hs[1] << 16);
        ho.y = (uint32_t)hs[2] | ((uint32_t)hs[3] << 16);
        lu.x = (uint32_t)ls[0] | ((uint32_t)ls[1] << 16);
        lu.y = (uint32_t)ls[2] | ((uint32_t)ls[3] << 16);
        h2[i] = ho;
        l2[i] = lu;
    }
}

// =================================================================
// Kernel 1: HMMA bf16 hi/lo GEMM + fused online-softmax partials
//   grid (16, 125, 2), block 512 (16 warps: 4m x 4n), warp tile 32x64
//   4-stage cp.async ring
// =================================================================
__device__ __forceinline__ void cp_tile(uint32_t dst, const __nv_bfloat16* src,
                                        int nchunks, int tid)
{
    for (int idx = tid; idx < nchunks; idx += NTHREADS) {
        int r = idx >> 2;
        int c = idx & 3;
        uint32_t off = (uint32_t)r * 64u + (uint32_t)c * 16u;
        const char* g = (const char*)src + (size_t)r * (HDIM * 2) + c * 16;
        asm volatile("cp.async.cg.shared.global [%0], [%1], 16;"
                     :: "r"(dst + swz64(off)), "l"(g) : "memory");
    }
}

__global__ __launch_bounds__(NTHREADS, 1)
void lse_mma_kernel(const float* __restrict__ b0v, const float* __restrict__ b1v)
{
    extern __shared__ char dsm[];
    __shared__ float bias_sm[TILE_N];
    __shared__ float redM[4][TILE_M];
    __shared__ float redS[4][TILE_M];

    const int tid  = threadIdx.x;
    const int wid  = tid >> 5;
    const int lane = tid & 31;
    const int warp_m = wid & 3;        // 0..3 (32 rows each)
    const int warp_n = wid >> 2;       // 0..3 (64 cols each)

    uint32_t raw  = smem_u32(dsm);
    uint32_t base = (raw + 1023u) & ~1023u;

    const int m0   = blockIdx.x * TILE_M;
    const int n0   = blockIdx.y * TILE_N;
    const int pass = blockIdx.z;
    const float* BV = pass ? b1v : b0v;

    const __nv_bfloat16* Ah = g_xhi + ((size_t)pass * BT + m0) * HDIM;
    const __nv_bfloat16* Al = g_xlo + ((size_t)pass * BT + m0) * HDIM;
    const __nv_bfloat16* Bh = g_whi + ((size_t)pass * VOCAB + n0) * HDIM;
    const __nv_bfloat16* Bl = g_wlo + ((size_t)pass * VOCAB + n0) * HDIM;

    if (tid < TILE_N) bias_sm[tid] = BV[n0 + tid];

    // per-lane ldmatrix offsets (tile-relative, swizzled)
    uint32_t aoff[2][2], boff[2][4];
    #pragma unroll
    for (int ks = 0; ks < 2; ks++) {
        #pragma unroll
        for (int mi = 0; mi < 2; mi++) {
            uint32_t row = (uint32_t)(warp_m * 32 + mi * 16 + (lane & 15));
            uint32_t kb  = (uint32_t)(ks * 32 + (lane >> 4) * 16);
            aoff[ks][mi] = swz64(row * 64u + kb);
        }
        #pragma unroll
        for (int np = 0; np < 4; np++) {
            uint32_t n  = (uint32_t)(warp_n * 64 + np * 16 + ((lane >> 4) & 1) * 8 + (lane & 7));
            uint32_t kb = (uint32_t)(ks * 32 + ((lane >> 3) & 1) * 16);
            boff[ks][np] = swz64(n * 64u + kb);
        }
    }

    float acc[2][8][4];
    #pragma unroll
    for (int mi = 0; mi < 2; mi++)
        #pragma unroll
        for (int ni = 0; ni < 8; ni++)
            #pragma unroll
            for (int j = 0; j < 4; j++) acc[mi][ni][j] = 0.0f;

    // prologue: fill stages 0..2
    #pragma unroll
    for (int p = 0; p < 3; p++) {
        const int k0 = p * KSTAGE;
        cp_tile(base + SM_AH(p), Ah + k0, TILE_M * 4, tid);
        cp_tile(base + SM_AL(p), Al + k0, TILE_M * 4, tid);
        cp_tile(base + SM_BH(p), Bh + k0, TILE_N * 4, tid);
        cp_tile(base + SM_BL(p), Bl + k0, TILE_N * 4, tid);
        asm volatile("cp.async.commit_group;" ::: "memory");
    }

    #pragma unroll 1
    for (int s = 0; s < NSTAGES; s++) {
        const int b = s & 3;
        asm volatile("cp.async.wait_group 2;" ::: "memory");
        __syncthreads();

        // issue loads for stage s+3 into slot (s+3)&3 (consumed in stage s-1)
        if (s + 3 < NSTAGES) {
            const int k0 = (s + 3) * KSTAGE;
            const int nb = (s + 3) & 3;
            cp_tile(base + SM_AH(nb), Ah + k0, TILE_M * 4, tid);
            cp_tile(base + SM_AL(nb), Al + k0, TILE_M * 4, tid);
            cp_tile(base + SM_BH(nb), Bh + k0, TILE_N * 4, tid);
            cp_tile(base + SM_BL(nb), Bl + k0, TILE_N * 4, tid);
        }
        asm volatile("cp.async.commit_group;" ::: "memory");

        const uint32_t bAh = base + SM_AH(b);
        const uint32_t bAl = base + SM_AL(b);
        const uint32_t bBh = base + SM_BH(b);
        const uint32_t bBl = base + SM_BL(b);

        #pragma unroll
        for (int ks = 0; ks < 2; ks++) {
            // sequenced to cap live fragments: {afh,bfh} -> +afl -> swap to bfl
            uint32_t afh[2][4];
            #pragma unroll
            for (int mi = 0; mi < 2; mi++) ldmatrix_x4(afh[mi], bAh + aoff[ks][mi]);
            uint32_t bfh[4][4];
            #pragma unroll
            for (int np = 0; np < 4; np++) ldmatrix_x4(bfh[np], bBh + boff[ks][np]);
            // combo 0: Ah*Bh
            #pragma unroll
            for (int mi = 0; mi < 2; mi++)
                #pragma unroll
                for (int ni = 0; ni < 8; ni++)
                    mma16816(acc[mi][ni], afh[mi],
                             bfh[ni >> 1][(ni & 1) * 2], bfh[ni >> 1][(ni & 1) * 2 + 1]);
            {
                uint32_t afl[2][4];
                #pragma unroll
                for (int mi = 0; mi < 2; mi++) ldmatrix_x4(afl[mi], bAl + aoff[ks][mi]);
                // combo 2: Al*Bh
                #pragma unroll
                for (int mi = 0; mi < 2; mi++)
                    #pragma unroll
                    for (int ni = 0; ni < 8; ni++)
                        mma16816(acc[mi][ni], afl[mi],
                                 bfh[ni >> 1][(ni & 1) * 2], bfh[ni >> 1][(ni & 1) * 2 + 1]);
            }
            {
                uint32_t bfl[4][4];
                #pragma unroll
                for (int np = 0; np < 4; np++) ldmatrix_x4(bfl[np], bBl + boff[ks][np]);
                // combo 1: Ah*Bl
                #pragma unroll
                for (int mi = 0; mi < 2; mi++)
                    #pragma unroll
                    for (int ni = 0; ni < 8; ni++)
                        mma16816(acc[mi][ni], afh[mi],
                                 bfl[ni >> 1][(ni & 1) * 2], bfl[ni >> 1][(ni & 1) * 2 + 1]);
            }
        }
    }

    // ---------------- epilogue: bias + online softmax ----------------
    const int q  = lane >> 2;     // row within 8
    const int tq = lane & 3;      // col pair selector

    #pragma unroll
    for (int mi = 0; mi < 2; mi++) {
        #pragma unroll
        for (int half = 0; half < 2; half++) {
            float v[16];
            #pragma unroll
            for (int ni = 0; ni < 8; ni++) {
                int col = warp_n * 64 + ni * 8 + tq * 2;
                v[ni * 2 + 0] = acc[mi][ni][half * 2 + 0] + bias_sm[col];
                v[ni * 2 + 1] = acc[mi][ni][half * 2 + 1] + bias_sm[col + 1];
            }
            float M = v[0];
            #pragma unroll
            for (int j = 1; j < 16; j++) M = fmaxf(M, v[j]);
            float S = 0.0f;
            #pragma unroll
            for (int j = 0; j < 16; j++) S += __expf(v[j] - M);
            #pragma unroll
            for (int o = 1; o <= 2; o <<= 1) {
                float oM = __shfl_xor_sync(0xffffffffu, M, o);
                float oS = __shfl_xor_sync(0xffffffffu, S, o);
                float nm = fmaxf(M, oM);
                S = S * __expf(M - nm) + oS * __expf(oM - nm);
                M = nm;
            }
            if (tq == 0) {
                int row = warp_m * 32 + mi * 16 + half * 8 + q;
                redM[warp_n][row] = M;
                redS[warp_n][row] = S;
            }
        }
    }
    __syncthreads();

    if (tid < TILE_M) {
        float M = redM[0][tid], S = redS[0][tid];
        #pragma unroll
        for (int w = 1; w < 4; w++) {
            float oM = redM[w][tid], oS = redS[w][tid];
            float nm = fmaxf(M, oM);
            S = S * __expf(M - nm) + oS * __expf(oM - nm);
            M = nm;
        }
        g_partials[pass][(size_t)blockIdx.y * BT + m0 + tid] = make_float2(M, S);
    }
}

// =================================================================
// Kernel 2: exact fp32 target logits
// =================================================================
__global__ __launch_bounds__(128)
void tgt_logit_kernel(const float* __restrict__ x0, const float* __restrict__ w0,
                      const float* __restrict__ b0,
                      const float* __restrict__ x1, const float* __restrict__ w1,
                      const float* __restrict__ b1, const void* __restrict__ tgt)
{
    const int pass = blockIdx.y;
    const float* X  = pass ? x1 : x0;
    const float* W  = pass ? w1 : w0;
    const float* BV = pass ? b1 : b0;
    const int tok = blockIdx.x;

    const bool is64 = target_is_i64(tgt);
    long long t = load_tgt(tgt, tok, is64);
    int tc = (int)t;
    tc = tc < 0 ? 0 : (tc >= VOCAB ? VOCAB - 1 : tc);

    const float4* xv = (const float4*)(X + (size_t)tok * HDIM);
    const float4* wv = (const float4*)(W + (size_t)tc * HDIM);
    float s = 0.0f;
    for (int c = threadIdx.x; c < HDIM / 4; c += blockDim.x) {
        float4 a = xv[c], b = wv[c];
        s += a.x * b.x + a.y * b.y + a.z * b.z + a.w * b.w;
    }
    #pragma unroll
    for (int o = 16; o; o >>= 1) s += __shfl_xor_sync(0xffffffffu, s, o);
    __shared__ float red[4];
    if ((threadIdx.x & 31) == 0) red[threadIdx.x >> 5] = s;
    __syncthreads();
    if (threadIdx.x == 0)
        g_tgt[pass][tok] = red[0] + red[1] + red[2] + red[3] + BV[tc];
}

// =================================================================
// Kernel 3: combine partials -> per-seq sums
// =================================================================
__global__ __launch_bounds__(256)
void combine_kernel(const void* __restrict__ tgt)
{
    const int b = blockIdx.x;
    const int tid = threadIdx.x;
    const bool is64 = target_is_i64(tgt);
    float accp = 0.0f, accr = 0.0f;

    for (int it = 0; it < TSEQ; it += 256) {
        const int tok = b * TSEQ + it + tid;
        long long t = load_tgt(tgt, tok, is64);
        if (t != IGNORE_INDEX) {
            #pragma unroll
            for (int p = 0; p < 2; p++) {
                float M = -INFINITY, S = 0.0f;
                #pragma unroll 1
                for (int c = 0; c < NTILES_N; c++) {
                    float2 pc = g_partials[p][(size_t)c * BT + tok];
                    float nm = fmaxf(M, pc.x);
                    S = S * __expf(M - nm) + pc.y * __expf(pc.x - nm);
                    M = nm;
                }
                float lp = g_tgt[p][tok] - (M + logf(S));
                if (p == 0) accp += lp; else accr += lp;
            }
        }
    }
    #pragma unroll
    for (int o = 16; o; o >>= 1) {
        accp += __shfl_xor_sync(0xffffffffu, accp, o);
        accr += __shfl_xor_sync(0xffffffffu, accr, o);
    }
    __shared__ float sp[8], sr[8];
    if ((tid & 31) == 0) { sp[tid >> 5] = accp; sr[tid >> 5] = accr; }
    __syncthreads();
    if (tid == 0) {
        float a = 0.0f, r = 0.0f;
        #pragma unroll
        for (int i = 0; i < 8; i++) { a += sp[i]; r += sr[i]; }
        g_seq[0][b] = a;
        g_seq[1][b] = r;
    }
}

// =================================================================
// Kernel 4: final KTO loss
// =================================================================
__global__ void final_kernel(const void* __restrict__ pref,
                             const float* __restrict__ kl,
                             float* __restrict__ out, int out_size)
{
    if (threadIdx.x != 0) return;
    const int* pw = (const int*)pref;
    bool isInt = true;
    int li[BSEQ];
    #pragma unroll
    for (int i = 0; i < BSEQ; i++) {
        int v = pw[i];
        if (v != 0 && v != 1) isInt = false;
        li[i] = v;
    }
    const unsigned char* pb = (const unsigned char*)pref;
    int lab[BSEQ];
    #pragma unroll
    for (int i = 0; i < BSEQ; i++)
        lab[i] = isInt ? li[i] : (pb[i] != 0 ? 1 : 0);

    const float kl0 = kl[0];
    float loss = 0.0f, ch = 0.0f, rj = 0.0f;
    #pragma unroll
    for (int b = 0; b < BSEQ; b++) {
        float lr   = g_seq[0][b] - g_seq[1][b];
        float mult = lab[b] ? 1.0f : -1.0f;
        float z    = BETA * (lr - kl0) * mult;
        loss += 1.0f - 1.0f / (1.0f + expf(-z));
        float rw = BETA * lr;
        if (lab[b]) ch += rw; else rj += rw;
    }
    loss /= (float)BT;
    if (out_size > 0) out[0] = loss;
    if (out_size > 1) out[1] = ch;
    if (out_size > 2) out[2] = rj;
}

// =================================================================
extern "C" void kernel_launch(void* const* d_in, const int* in_sizes, int n_in,
                              void* d_out, int out_size)
{
    const float* x    = (const float*)d_in[0];
    const float* w    = (const float*)d_in[1];
    const void*  tgt  = d_in[2];
    const float* bias = (const float*)d_in[3];
    const void*  pref = d_in[4];
    const float* xr   = (const float*)d_in[5];
    const float* wr   = (const float*)d_in[6];
    const float* br   = (const float*)d_in[7];
    const float* kl   = (const float*)d_in[8];

    __nv_bfloat16 *whi, *wlo, *xhi, *xlo;
    cudaGetSymbolAddress((void**)&whi, g_whi);
    cudaGetSymbolAddress((void**)&wlo, g_wlo);
    cudaGetSymbolAddress((void**)&xhi, g_xhi);
    cudaGetSymbolAddress((void**)&xlo, g_xlo);

    const long long WN4 = (long long)VOCAB * HDIM / 4;
    const long long XN4 = (long long)BT * HDIM / 4;
    split_kernel<<<2048, 256>>>(w,  whi, wlo, WN4);
    split_kernel<<<2048, 256>>>(wr, whi + (size_t)VOCAB * HDIM,
                                     wlo + (size_t)VOCAB * HDIM, WN4);
    split_kernel<<<256, 256>>>(x,  xhi, xlo, XN4);
    split_kernel<<<256, 256>>>(xr, xhi + (size_t)BT * HDIM,
                                    xlo + (size_t)BT * HDIM, XN4);

    cudaFuncSetAttribute(lse_mma_kernel,
                         cudaFuncAttributeMaxDynamicSharedMemorySize, SMEM_DYN);
    dim3 g1(NTILES_M, NTILES_N, 2);
    lse_mma_kernel<<<g1, NTHREADS, SMEM_DYN>>>(bias, br);

    tgt_logit_kernel<<<dim3(BT, 2), 128>>>(x, w, bias, xr, wr, br, tgt);
    combine_kernel<<<BSEQ, 256>>>(tgt);
    final_kernel<<<1, 32>>>(pref, kl, (float*)d_out, out_size);
}